// round 16
// baseline (speedup 1.0000x reference)
#include <cuda_runtime.h>
#include <cuda_fp16.h>

#define NU 200000
#define NI 100000
#define NT 300000          // NU + NI
#define NE 4000000
#define NB ((NT + 1023) / 1024)   // scan blocks = 293
#define NBK 64             // degree buckets for block-local counting sort

// -------- device scratch (no allocations allowed) --------
// Row NT of each y-buffer is an all-zero sentinel row (padded edges point here).
__device__ __half2 g_a[(NT + 1) * 32];   // y0 (alive through layer 3 for x reconstruction)
__device__ __half2 g_b[(NT + 1) * 32];   // y1
__device__ __half2 g_c[(NT + 1) * 32];   // y2
__device__ int   g_deg[NT];
__device__ float g_dinv[NT];
__device__ int   g_rowptr[NT + 1]; // after scatter: rowptr[i] = END of row i
__device__ int   g_bsum[NB];
__device__ int   g_perm[NT];       // block-locally degree-sorted rows
__device__ int   g_col[NE + 256];  // dst, CSR-ordered by src (+slack for prefetch overread)

__device__ __forceinline__ __half2* buf(int s) {
    return (s == 0) ? g_a : (s == 1) ? g_b : g_c;
}

// -------- build: degree histogram --------
__global__ void k_hist(const int4* __restrict__ src4) {
    int i = blockIdx.x * blockDim.x + threadIdx.x;
    if (i < NE / 4) {
        int4 s = src4[i];
        atomicAdd(&g_deg[s.x], 1);
        atomicAdd(&g_deg[s.y], 1);
        atomicAdd(&g_deg[s.z], 1);
        atomicAdd(&g_deg[s.w], 1);
    }
}

// -------- build: scan phase A (dinv + block-local degree sort fused) --------
__global__ void __launch_bounds__(1024) k_scanA() {
    __shared__ int ws[32];
    __shared__ int bh[NBK];    // bucket counts
    __shared__ int bho[NBK];   // bucket cursors (exclusive bases)
    int i = blockIdx.x * 1024 + threadIdx.x;
    if (threadIdx.x < NBK) bh[threadIdx.x] = 0;
    int v = (i < NT) ? g_deg[i] : 0;
    if (i < NT) g_dinv[i] = rsqrtf((float)v + 1e-8f);
    int lane = threadIdx.x & 31, wid = threadIdx.x >> 5;
    int x = v;
    #pragma unroll
    for (int o = 1; o < 32; o <<= 1) {
        int y = __shfl_up_sync(0xffffffffu, x, o);
        if (lane >= o) x += y;
    }
    if (lane == 31) ws[wid] = x;
    __syncthreads();
    int bucket = v < NBK ? v : NBK - 1;
    if (i < NT) atomicAdd(&bh[bucket], 1);    // smem hist
    if (wid == 0) {
        int s = ws[lane];
        #pragma unroll
        for (int o = 1; o < 32; o <<= 1) {
            int y = __shfl_up_sync(0xffffffffu, s, o);
            if (lane >= o) s += y;
        }
        ws[lane] = s;
    }
    __syncthreads();
    // warp 1: exclusive scan of 64 bucket counts -> cursors
    if (wid == 1) {
        int b0 = bh[lane];
        int b1 = bh[lane + 32];
        int x0 = b0;
        #pragma unroll
        for (int o = 1; o < 32; o <<= 1) {
            int y = __shfl_up_sync(0xffffffffu, x0, o);
            if (lane >= o) x0 += y;
        }
        int tot0 = __shfl_sync(0xffffffffu, x0, 31);
        int x1 = b1;
        #pragma unroll
        for (int o = 1; o < 32; o <<= 1) {
            int y = __shfl_up_sync(0xffffffffu, x1, o);
            if (lane >= o) x1 += y;
        }
        bho[lane]      = x0 - b0;
        bho[lane + 32] = x1 - b1 + tot0;
    }
    int excl = x - v + (wid > 0 ? ws[wid - 1] : 0);
    if (i < NT) g_rowptr[i] = excl;
    if (threadIdx.x == 1023) g_bsum[blockIdx.x] = ws[31];
    __syncthreads();
    if (i < NT) {
        int p = atomicAdd(&bho[bucket], 1);   // smem rank within block
        g_perm[blockIdx.x * 1024 + p] = i;
    }
}

// -------- build: scan phase B --------
__global__ void k_scanB() {
    __shared__ int ws[16];
    int t = threadIdx.x;
    int v = (t < NB) ? g_bsum[t] : 0;
    int lane = t & 31, wid = t >> 5;
    int x = v;
    #pragma unroll
    for (int o = 1; o < 32; o <<= 1) {
        int y = __shfl_up_sync(0xffffffffu, x, o);
        if (lane >= o) x += y;
    }
    if (lane == 31) ws[wid] = x;
    __syncthreads();
    if (wid == 0) {
        int s = (lane < 16) ? ws[lane] : 0;
        #pragma unroll
        for (int o = 1; o < 32; o <<= 1) {
            int y = __shfl_up_sync(0xffffffffu, s, o);
            if (lane >= o) s += y;
        }
        if (lane < 16) ws[lane] = s;
    }
    __syncthreads();
    int excl = x - v + (wid > 0 ? ws[wid - 1] : 0);
    if (t < NB) g_bsum[t] = excl;
}

// -------- fused: scanC + init (y0 = dinv*x fp16) + sentinel --------
__global__ void k_fixinit(const float4* __restrict__ uw, const float4* __restrict__ iw) {
    int i = blockIdx.x * blockDim.x + threadIdx.x;   // uint4 index into g_a: NT*8 (+8 sentinel)
    if (i < NT) g_rowptr[i] += g_bsum[i >> 10];
    const int NTQ = NT * 8;
    if (i >= NTQ + 8) return;
    if (i >= NTQ) {                                  // zero sentinel row NT in all buffers
        uint4 z = make_uint4(0u, 0u, 0u, 0u);
        ((uint4*)g_a)[i] = z;
        ((uint4*)g_b)[i] = z;
        ((uint4*)g_c)[i] = z;
        return;
    }
    int r = i >> 3;                                  // node
    float di = g_dinv[r];
    int fo = i * 2;                                  // float4 index into x
    const float4* xs = (r < NU) ? uw + fo : iw + (fo - NU * 16);
    float4 v0 = xs[0];
    float4 v1 = xs[1];
    __half2 h0 = __floats2half2_rn(di * v0.x, di * v0.y);
    __half2 h1 = __floats2half2_rn(di * v0.z, di * v0.w);
    __half2 h2 = __floats2half2_rn(di * v1.x, di * v1.y);
    __half2 h3 = __floats2half2_rn(di * v1.z, di * v1.w);
    uint4 raw;
    raw.x = *(const unsigned*)&h0;
    raw.y = *(const unsigned*)&h1;
    raw.z = *(const unsigned*)&h2;
    raw.w = *(const unsigned*)&h3;
    ((uint4*)g_a)[i] = raw;
}

// -------- build: scatter; cursor IS rowptr (rowptr[i] ends at row end) --------
__global__ void k_scatter(const int2* __restrict__ src2, const int2* __restrict__ dst2) {
    int i = blockIdx.x * blockDim.x + threadIdx.x;
    if (i < NE / 2) {
        int2 s = src2[i];
        int2 d = dst2[i];
        int p0 = atomicAdd(&g_rowptr[s.x], 1);
        g_col[p0] = d.x;
        int p1 = atomicAdd(&g_rowptr[s.y], 1);
        g_col[p1] = d.y;
    }
}

// -------- SpMM: 4 degree-matched rows per warp (block-local perm); uint4 ------
// Zero-row sentinel (col = NT) -> fully unconditional inner loop.
// Depth-2 fp16 HADD2 tree over groups of 4 edges, fp32 fold per group.
// Col loads software-pipelined. LAST=1: fused epilogue, x reconstructed from y0.
template<int S, int DBUF, int LAST>
__global__ void __launch_bounds__(256) k_spmm(float4* __restrict__ out) {
    int w = (blockIdx.x * 256 + threadIdx.x) >> 5;   // warp id: 0 .. NT/4-1
    if (w >= NT / 4) return;
    int lane  = threadIdx.x & 31;
    int lane8 = lane & 7;
    int seg   = lane >> 3;                           // 0..3
    int r = g_perm[w * 4 + seg];                     // degree-matched row

    const uint4* __restrict__ y = (const uint4*)buf(S);

    int end = g_rowptr[r];
    int n   = g_deg[r];
    int beg = end - n;
    // warp-wide max degree over the 4 segments (near-equal after local sort)
    int nMax = n;
    nMax = max(nMax, __shfl_xor_sync(0xffffffffu, nMax, 8));
    nMax = max(nMax, __shfl_xor_sync(0xffffffffu, nMax, 16));

    float a0 = 0.f, a1 = 0.f, a2 = 0.f, a3 = 0.f;
    float a4 = 0.f, a5 = 0.f, a6 = 0.f, a7 = 0.f;

    int t0 = g_col[beg + lane8];                     // slack array: always in bounds
    int myc = (lane8 < n) ? t0 : NT;                 // sentinel = zero row
    for (int base = 0; base < nMax; base += 8) {
        int ne = base + 8 + lane8;
        int tn = g_col[beg + ne];                    // may overread row (slack); SEL discards
        int nextc = (ne < n) ? tn : NT;
        #pragma unroll
        for (int k = 0; k < 8; k += 4) {
            int ca = __shfl_sync(0xffffffffu, myc, k + 0, 8);
            int cb = __shfl_sync(0xffffffffu, myc, k + 1, 8);
            int cc = __shfl_sync(0xffffffffu, myc, k + 2, 8);
            int cd = __shfl_sync(0xffffffffu, myc, k + 3, 8);
            uint4 ra = y[ca * 8 + lane8];            // unconditional
            uint4 rb = y[cb * 8 + lane8];
            uint4 rc = y[cc * 8 + lane8];
            uint4 rd = y[cd * 8 + lane8];
            // depth-2 fp16 tree: (a+b) + (c+d) per component
            __half2 s0 = __hadd2(__hadd2(*(const __half2*)&ra.x, *(const __half2*)&rb.x),
                                 __hadd2(*(const __half2*)&rc.x, *(const __half2*)&rd.x));
            __half2 s1 = __hadd2(__hadd2(*(const __half2*)&ra.y, *(const __half2*)&rb.y),
                                 __hadd2(*(const __half2*)&rc.y, *(const __half2*)&rd.y));
            __half2 s2 = __hadd2(__hadd2(*(const __half2*)&ra.z, *(const __half2*)&rb.z),
                                 __hadd2(*(const __half2*)&rc.z, *(const __half2*)&rd.z));
            __half2 s3 = __hadd2(__hadd2(*(const __half2*)&ra.w, *(const __half2*)&rb.w),
                                 __hadd2(*(const __half2*)&rc.w, *(const __half2*)&rd.w));
            float2 f0 = __half22float2(s0);
            float2 f1 = __half22float2(s1);
            float2 f2 = __half22float2(s2);
            float2 f3 = __half22float2(s3);
            a0 += f0.x; a1 += f0.y; a2 += f1.x; a3 += f1.y;
            a4 += f2.x; a5 += f2.y; a6 += f3.x; a7 += f3.y;
        }
        myc = nextc;
    }

    float di = g_dinv[r];
    int o = r * 8 + lane8;                           // uint4 index within y-layout
    if (!LAST) {
        float f = di * di;
        __half2 h0 = __floats2half2_rn(f * a0, f * a1);
        __half2 h1 = __floats2half2_rn(f * a2, f * a3);
        __half2 h2 = __floats2half2_rn(f * a4, f * a5);
        __half2 h3 = __floats2half2_rn(f * a6, f * a7);
        uint4 raw;
        raw.x = *(const unsigned*)&h0;
        raw.y = *(const unsigned*)&h1;
        raw.z = *(const unsigned*)&h2;
        raw.w = *(const unsigned*)&h3;
        ((uint4*)buf(DBUF))[o] = raw;
    } else {
        // h3 = di*s; x = inv*y0; out = 0.25*(inv*(y0+y1+y2) + di*s)
        float inv = __frcp_rn(di);                   // = sqrt(deg + 1e-8)
        uint4 ra = ((const uint4*)g_a)[o];
        uint4 rb = ((const uint4*)g_b)[o];
        uint4 rc = ((const uint4*)g_c)[o];
        float2 A0 = __half22float2(*(const __half2*)&ra.x);
        float2 A1 = __half22float2(*(const __half2*)&ra.y);
        float2 A2 = __half22float2(*(const __half2*)&ra.z);
        float2 A3 = __half22float2(*(const __half2*)&ra.w);
        float2 B0 = __half22float2(*(const __half2*)&rb.x);
        float2 B1 = __half22float2(*(const __half2*)&rb.y);
        float2 B2 = __half22float2(*(const __half2*)&rb.z);
        float2 B3 = __half22float2(*(const __half2*)&rb.w);
        float2 C0 = __half22float2(*(const __half2*)&rc.x);
        float2 C1 = __half22float2(*(const __half2*)&rc.y);
        float2 C2 = __half22float2(*(const __half2*)&rc.z);
        float2 C3 = __half22float2(*(const __half2*)&rc.w);
        int fo = r * 16 + lane8 * 2;                 // float4 index (row = 16 float4)
        out[fo] = make_float4(
            0.25f * (inv * (A0.x + B0.x + C0.x) + di * a0),
            0.25f * (inv * (A0.y + B0.y + C0.y) + di * a1),
            0.25f * (inv * (A1.x + B1.x + C1.x) + di * a2),
            0.25f * (inv * (A1.y + B1.y + C1.y) + di * a3));
        out[fo + 1] = make_float4(
            0.25f * (inv * (A2.x + B2.x + C2.x) + di * a4),
            0.25f * (inv * (A2.y + B2.y + C2.y) + di * a5),
            0.25f * (inv * (A3.x + B3.x + C3.x) + di * a6),
            0.25f * (inv * (A3.y + B3.y + C3.y) + di * a7));
    }
}

extern "C" void kernel_launch(void* const* d_in, const int* in_sizes, int n_in,
                              void* d_out, int out_size) {
    const float* uw  = (const float*)d_in[0];
    const float* iw  = (const float*)d_in[1];
    const int*   src = (const int*)d_in[2];
    const int*   dst = (const int*)d_in[3];
    float* out = (float*)d_out;

    // zero deg via memset node
    void *p_deg = nullptr;
    cudaGetSymbolAddress(&p_deg, g_deg);
    cudaMemsetAsync(p_deg, 0, NT * sizeof(int));

    // CSR build + init
    k_hist<<<(NE / 4 + 255) / 256, 256>>>((const int4*)src);
    k_scanA<<<NB, 1024>>>();
    k_scanB<<<1, 512>>>();
    k_fixinit<<<(NT * 8 + 8 + 255) / 256, 256>>>((const float4*)uw, (const float4*)iw);
    k_scatter<<<(NE / 2 + 255) / 256, 256>>>((const int2*)src, (const int2*)dst);

    // 3 propagation layers; 4 degree-matched rows per warp
    int nblk = (NT / 4 * 32 + 255) / 256;
    k_spmm<0, 1, 0><<<nblk, 256>>>((float4*)out);
    k_spmm<1, 2, 0><<<nblk, 256>>>((float4*)out);
    k_spmm<2, 0, 1><<<nblk, 256>>>((float4*)out);
}

// round 17
// speedup vs baseline: 1.0912x; 1.0912x over previous
#include <cuda_runtime.h>
#include <cuda_fp16.h>

#define NU 200000
#define NI 100000
#define NT 300000          // NU + NI
#define NE 4000000
#define NB ((NT + 1023) / 1024)   // scan blocks = 293
#define NBK 64             // degree buckets for block-local counting sort

// -------- device scratch (no allocations allowed) --------
// Row NT of each y-buffer is an all-zero sentinel row (padded edges point here).
__device__ __half2 g_a[(NT + 1) * 32];   // y0 (alive through layer 3 for x reconstruction)
__device__ __half2 g_b[(NT + 1) * 32];   // y1
__device__ __half2 g_c[(NT + 1) * 32];   // y2
__device__ int   g_deg[NT];
__device__ float g_dinv[NT];
__device__ int   g_rowptr[NT + 1]; // after scatter: rowptr[i] = END of row i
__device__ int   g_bsum[NB];
__device__ int   g_perm[NT];       // block-locally degree-sorted rows; deg packed in bits 19..31
__device__ int   g_col[NE + 256];  // dst, CSR-ordered by src (+slack for prefetch overread)

__device__ __forceinline__ __half2* buf(int s) {
    return (s == 0) ? g_a : (s == 1) ? g_b : g_c;
}

// -------- build: degree histogram --------
__global__ void k_hist(const int4* __restrict__ src4) {
    int i = blockIdx.x * blockDim.x + threadIdx.x;
    if (i < NE / 4) {
        int4 s = src4[i];
        atomicAdd(&g_deg[s.x], 1);
        atomicAdd(&g_deg[s.y], 1);
        atomicAdd(&g_deg[s.z], 1);
        atomicAdd(&g_deg[s.w], 1);
    }
}

// -------- build: scan phase A (dinv + block-local degree sort fused) --------
__global__ void __launch_bounds__(1024) k_scanA() {
    __shared__ int ws[32];
    __shared__ int bh[NBK];    // bucket counts
    __shared__ int bho[NBK];   // bucket cursors (exclusive bases)
    int i = blockIdx.x * 1024 + threadIdx.x;
    if (threadIdx.x < NBK) bh[threadIdx.x] = 0;
    int v = (i < NT) ? g_deg[i] : 0;
    if (i < NT) g_dinv[i] = rsqrtf((float)v + 1e-8f);
    int lane = threadIdx.x & 31, wid = threadIdx.x >> 5;
    int x = v;
    #pragma unroll
    for (int o = 1; o < 32; o <<= 1) {
        int y = __shfl_up_sync(0xffffffffu, x, o);
        if (lane >= o) x += y;
    }
    if (lane == 31) ws[wid] = x;
    __syncthreads();
    int bucket = v < NBK ? v : NBK - 1;
    if (i < NT) atomicAdd(&bh[bucket], 1);    // smem hist
    if (wid == 0) {
        int s = ws[lane];
        #pragma unroll
        for (int o = 1; o < 32; o <<= 1) {
            int y = __shfl_up_sync(0xffffffffu, s, o);
            if (lane >= o) s += y;
        }
        ws[lane] = s;
    }
    __syncthreads();
    // warp 1: exclusive scan of 64 bucket counts -> cursors
    if (wid == 1) {
        int b0 = bh[lane];
        int b1 = bh[lane + 32];
        int x0 = b0;
        #pragma unroll
        for (int o = 1; o < 32; o <<= 1) {
            int y = __shfl_up_sync(0xffffffffu, x0, o);
            if (lane >= o) x0 += y;
        }
        int tot0 = __shfl_sync(0xffffffffu, x0, 31);
        int x1 = b1;
        #pragma unroll
        for (int o = 1; o < 32; o <<= 1) {
            int y = __shfl_up_sync(0xffffffffu, x1, o);
            if (lane >= o) x1 += y;
        }
        bho[lane]      = x0 - b0;
        bho[lane + 32] = x1 - b1 + tot0;
    }
    int excl = x - v + (wid > 0 ? ws[wid - 1] : 0);
    if (i < NT) g_rowptr[i] = excl;
    if (threadIdx.x == 1023) g_bsum[blockIdx.x] = ws[31];
    __syncthreads();
    if (i < NT) {
        int p = atomicAdd(&bho[bucket], 1);   // smem rank within block
        int dpk = v < 8191 ? v : 8191;        // pack deg (clamped; fallback in spmm)
        g_perm[blockIdx.x * 1024 + p] = i | (dpk << 19);
    }
}

// -------- build: scan phase B --------
__global__ void k_scanB() {
    __shared__ int ws[16];
    int t = threadIdx.x;
    int v = (t < NB) ? g_bsum[t] : 0;
    int lane = t & 31, wid = t >> 5;
    int x = v;
    #pragma unroll
    for (int o = 1; o < 32; o <<= 1) {
        int y = __shfl_up_sync(0xffffffffu, x, o);
        if (lane >= o) x += y;
    }
    if (lane == 31) ws[wid] = x;
    __syncthreads();
    if (wid == 0) {
        int s = (lane < 16) ? ws[lane] : 0;
        #pragma unroll
        for (int o = 1; o < 32; o <<= 1) {
            int y = __shfl_up_sync(0xffffffffu, s, o);
            if (lane >= o) s += y;
        }
        if (lane < 16) ws[lane] = s;
    }
    __syncthreads();
    int excl = x - v + (wid > 0 ? ws[wid - 1] : 0);
    if (t < NB) g_bsum[t] = excl;
}

// -------- fused: scanC + init (y0 = dinv*x fp16) + sentinel --------
__global__ void k_fixinit(const float4* __restrict__ uw, const float4* __restrict__ iw) {
    int i = blockIdx.x * blockDim.x + threadIdx.x;   // uint4 index into g_a: NT*8 (+8 sentinel)
    if (i < NT) g_rowptr[i] += g_bsum[i >> 10];
    const int NTQ = NT * 8;
    if (i >= NTQ + 8) return;
    if (i >= NTQ) {                                  // zero sentinel row NT in all buffers
        uint4 z = make_uint4(0u, 0u, 0u, 0u);
        ((uint4*)g_a)[i] = z;
        ((uint4*)g_b)[i] = z;
        ((uint4*)g_c)[i] = z;
        return;
    }
    int r = i >> 3;                                  // node
    float di = g_dinv[r];
    int fo = i * 2;                                  // float4 index into x
    const float4* xs = (r < NU) ? uw + fo : iw + (fo - NU * 16);
    float4 v0 = xs[0];
    float4 v1 = xs[1];
    __half2 h0 = __floats2half2_rn(di * v0.x, di * v0.y);
    __half2 h1 = __floats2half2_rn(di * v0.z, di * v0.w);
    __half2 h2 = __floats2half2_rn(di * v1.x, di * v1.y);
    __half2 h3 = __floats2half2_rn(di * v1.z, di * v1.w);
    uint4 raw;
    raw.x = *(const unsigned*)&h0;
    raw.y = *(const unsigned*)&h1;
    raw.z = *(const unsigned*)&h2;
    raw.w = *(const unsigned*)&h3;
    ((uint4*)g_a)[i] = raw;
}

// -------- build: scatter; cursor IS rowptr (rowptr[i] ends at row end) --------
__global__ void k_scatter(const int2* __restrict__ src2, const int2* __restrict__ dst2) {
    int i = blockIdx.x * blockDim.x + threadIdx.x;
    if (i < NE / 2) {
        int2 s = src2[i];
        int2 d = dst2[i];
        int p0 = atomicAdd(&g_rowptr[s.x], 1);
        g_col[p0] = d.x;
        int p1 = atomicAdd(&g_rowptr[s.y], 1);
        g_col[p1] = d.y;
    }
}

// -------- SpMM: 4 degree-matched rows per warp (block-local perm); uint4 ------
// Zero-row sentinel (col = NT) -> fully unconditional inner loop.
// Pairwise HADD2 pre-reduction, fp32 fold per pair. Col loads software-pipelined.
// deg packed in perm bits 19..31 (fallback load if clamped).
// LAST=1: fused epilogue, x reconstructed from y0; cache-streaming hints.
template<int S, int DBUF, int LAST>
__global__ void __launch_bounds__(256) k_spmm(float4* __restrict__ out) {
    int w = (blockIdx.x * 256 + threadIdx.x) >> 5;   // warp id: 0 .. NT/4-1
    if (w >= NT / 4) return;
    int lane  = threadIdx.x & 31;
    int lane8 = lane & 7;
    int seg   = lane >> 3;                           // 0..3
    int pr = g_perm[w * 4 + seg];                    // packed: row | (deg<<19)
    int r  = pr & 0x7FFFF;
    int n  = pr >> 19;
    if (n == 8191) n = g_deg[r];                     // clamp fallback (never in practice)

    const uint4* __restrict__ y = (const uint4*)buf(S);

    int end = g_rowptr[r];
    int beg = end - n;
    // warp-wide max degree over the 4 segments (near-equal after local sort)
    int nMax = n;
    nMax = max(nMax, __shfl_xor_sync(0xffffffffu, nMax, 8));
    nMax = max(nMax, __shfl_xor_sync(0xffffffffu, nMax, 16));

    float a0 = 0.f, a1 = 0.f, a2 = 0.f, a3 = 0.f;
    float a4 = 0.f, a5 = 0.f, a6 = 0.f, a7 = 0.f;

    int t0 = g_col[beg + lane8];                     // slack array: always in bounds
    int myc = (lane8 < n) ? t0 : NT;                 // sentinel = zero row
    for (int base = 0; base < nMax; base += 8) {
        int ne = base + 8 + lane8;
        int tn = g_col[beg + ne];                    // may overread row (slack); SEL discards
        int nextc = (ne < n) ? tn : NT;
        #pragma unroll
        for (int k = 0; k < 8; k += 2) {
            int ca = __shfl_sync(0xffffffffu, myc, k + 0, 8);
            int cb = __shfl_sync(0xffffffffu, myc, k + 1, 8);
            uint4 ra = y[ca * 8 + lane8];            // unconditional
            uint4 rb = y[cb * 8 + lane8];            // unconditional
            __half2 s0 = __hadd2(*(const __half2*)&ra.x, *(const __half2*)&rb.x);
            __half2 s1 = __hadd2(*(const __half2*)&ra.y, *(const __half2*)&rb.y);
            __half2 s2 = __hadd2(*(const __half2*)&ra.z, *(const __half2*)&rb.z);
            __half2 s3 = __hadd2(*(const __half2*)&ra.w, *(const __half2*)&rb.w);
            float2 f0 = __half22float2(s0);
            float2 f1 = __half22float2(s1);
            float2 f2 = __half22float2(s2);
            float2 f3 = __half22float2(s3);
            a0 += f0.x; a1 += f0.y; a2 += f1.x; a3 += f1.y;
            a4 += f2.x; a5 += f2.y; a6 += f3.x; a7 += f3.y;
        }
        myc = nextc;
    }

    float di = g_dinv[r];
    int o = r * 8 + lane8;                           // uint4 index within y-layout
    if (!LAST) {
        float f = di * di;
        __half2 h0 = __floats2half2_rn(f * a0, f * a1);
        __half2 h1 = __floats2half2_rn(f * a2, f * a3);
        __half2 h2 = __floats2half2_rn(f * a4, f * a5);
        __half2 h3 = __floats2half2_rn(f * a6, f * a7);
        uint4 raw;
        raw.x = *(const unsigned*)&h0;
        raw.y = *(const unsigned*)&h1;
        raw.z = *(const unsigned*)&h2;
        raw.w = *(const unsigned*)&h3;
        ((uint4*)buf(DBUF))[o] = raw;
    } else {
        // h3 = di*s; x = inv*y0; out = 0.25*(inv*(y0+y1+y2) + di*s)
        float inv = __frcp_rn(di);                   // = sqrt(deg + 1e-8)
        uint4 ra = __ldcs(((const uint4*)g_a) + o);  // last use: evict-first
        uint4 rb = __ldcs(((const uint4*)g_b) + o);  // last use: evict-first
        uint4 rc = ((const uint4*)g_c)[o];           // also the gather source: keep resident
        float2 A0 = __half22float2(*(const __half2*)&ra.x);
        float2 A1 = __half22float2(*(const __half2*)&ra.y);
        float2 A2 = __half22float2(*(const __half2*)&ra.z);
        float2 A3 = __half22float2(*(const __half2*)&ra.w);
        float2 B0 = __half22float2(*(const __half2*)&rb.x);
        float2 B1 = __half22float2(*(const __half2*)&rb.y);
        float2 B2 = __half22float2(*(const __half2*)&rb.z);
        float2 B3 = __half22float2(*(const __half2*)&rb.w);
        float2 C0 = __half22float2(*(const __half2*)&rc.x);
        float2 C1 = __half22float2(*(const __half2*)&rc.y);
        float2 C2 = __half22float2(*(const __half2*)&rc.z);
        float2 C3 = __half22float2(*(const __half2*)&rc.w);
        int fo = r * 16 + lane8 * 2;                 // float4 index (row = 16 float4)
        float4 o0 = make_float4(
            0.25f * (inv * (A0.x + B0.x + C0.x) + di * a0),
            0.25f * (inv * (A0.y + B0.y + C0.y) + di * a1),
            0.25f * (inv * (A1.x + B1.x + C1.x) + di * a2),
            0.25f * (inv * (A1.y + B1.y + C1.y) + di * a3));
        float4 o1 = make_float4(
            0.25f * (inv * (A2.x + B2.x + C2.x) + di * a4),
            0.25f * (inv * (A2.y + B2.y + C2.y) + di * a5),
            0.25f * (inv * (A3.x + B3.x + C3.x) + di * a6),
            0.25f * (inv * (A3.y + B3.y + C3.y) + di * a7));
        __stcs(out + fo, o0);                        // write-once: don't pollute L2
        __stcs(out + fo + 1, o1);
    }
}

extern "C" void kernel_launch(void* const* d_in, const int* in_sizes, int n_in,
                              void* d_out, int out_size) {
    const float* uw  = (const float*)d_in[0];
    const float* iw  = (const float*)d_in[1];
    const int*   src = (const int*)d_in[2];
    const int*   dst = (const int*)d_in[3];
    float* out = (float*)d_out;

    // zero deg via memset node
    void *p_deg = nullptr;
    cudaGetSymbolAddress(&p_deg, g_deg);
    cudaMemsetAsync(p_deg, 0, NT * sizeof(int));

    // CSR build + init
    k_hist<<<(NE / 4 + 255) / 256, 256>>>((const int4*)src);
    k_scanA<<<NB, 1024>>>();
    k_scanB<<<1, 512>>>();
    k_fixinit<<<(NT * 8 + 8 + 255) / 256, 256>>>((const float4*)uw, (const float4*)iw);
    k_scatter<<<(NE / 2 + 255) / 256, 256>>>((const int2*)src, (const int2*)dst);

    // 3 propagation layers; 4 degree-matched rows per warp
    int nblk = (NT / 4 * 32 + 255) / 256;
    k_spmm<0, 1, 0><<<nblk, 256>>>((float4*)out);
    k_spmm<1, 2, 0><<<nblk, 256>>>((float4*)out);
    k_spmm<2, 0, 1><<<nblk, 256>>>((float4*)out);
}